// round 3
// baseline (speedup 1.0000x reference)
#include <cuda_runtime.h>
#include <cuda_fp16.h>
#include <cstdint>

#define NSER 8
#define NLAY 4
#define HDIM 256
#define TILE_M 128
#define THREADS 256

// ---- smem layout (byte offsets from 1024-aligned base) ----
#define SM_A    0                       // 128x256 fp16, SW128 blocked atoms (65536 B)
#define SM_B    65536                   // 256x256 fp16, SW128 blocked atoms (131072 B)
#define SM_BH   196608                  // bias double buffer 2 x 1024 B
#define SM_W0   198656                  // W0 stage 3072 B (reused as reduction buf)
#define SM_B0   201728                  // b0 stage 1024 B
#define SM_RED  SM_W0                   // 4 x 128 floats (2048 B), reuse W0 region
#define SMEM_BYTES (201728 + 1024 + 1024)   // + align slack

// Pre-swizzled fp16 weight tiles: [s*4+l] tiles, each 256(out j) x 256(in k)
__device__ __half g_Bw[(size_t)NSER * NLAY * HDIM * HDIM];

__device__ __forceinline__ uint32_t swz(uint32_t o) { return o ^ ((o >> 3) & 0x70); }

// B tile: 256 rows (out j) x 256 cols (k); SW128 blocked atoms, 32 atom-rows per k-block
__device__ __forceinline__ uint32_t b_off(int j, int k) {
    uint32_t o = ((uint32_t)(j >> 3) + (uint32_t)(k >> 6) * 32u) * 1024u
               + (uint32_t)(j & 7) * 128u + (uint32_t)(k & 63) * 2u;
    return swz(o);
}

__device__ __forceinline__ uint32_t s2u(const void* p) {
    uint32_t a;
    asm("{ .reg .u64 t; cvta.to.shared.u64 t, %1; cvt.u32.u64 %0, t; }" : "=r"(a) : "l"(p));
    return a;
}

__device__ __forceinline__ float softplusf(float x) {
    float ax = fabsf(x), u, lg;
    asm("ex2.approx.ftz.f32 %0, %1;" : "=f"(u) : "f"(-1.4426950408889634f * ax));
    asm("lg2.approx.ftz.f32 %0, %1;" : "=f"(lg) : "f"(1.0f + u));
    return fmaxf(x, 0.0f) + 0.6931471805599453f * lg;
}

__device__ __forceinline__ __half2 sp2(float a, float b) {
    return __floats2half2_rn(softplusf(a), softplusf(b));
}

// ---- prep: fp32 Wh[s][l][k][j] (k=in, j=out) -> fp16 pre-swizzled B images ----
__global__ void prep_weights(const float* __restrict__ Wh) {
    int idx = blockIdx.x * blockDim.x + threadIdx.x;
    if (idx >= NSER * NLAY * HDIM * HDIM) return;
    int t = idx >> 16;
    int r = idx & 0xFFFF;
    int k = r >> 8;          // input index
    int j = r & 0xFF;        // output index (fastest -> coalesced read)
    float w = Wh[((size_t)t << 16) + (k << 8) + j];
    char* base = (char*)g_Bw + (size_t)t * 131072;
    *(__half*)(base + b_off(j, k)) = __float2half_rn(w);
}

__device__ __forceinline__ void ldsm_x4(uint32_t& r0, uint32_t& r1, uint32_t& r2,
                                        uint32_t& r3, uint32_t a) {
    asm volatile("ldmatrix.sync.aligned.m8n8.x4.shared.b16 {%0,%1,%2,%3}, [%4];"
                 : "=r"(r0), "=r"(r1), "=r"(r2), "=r"(r3) : "r"(a));
}
__device__ __forceinline__ void ldsm_x2(uint32_t& r0, uint32_t& r1, uint32_t a) {
    asm volatile("ldmatrix.sync.aligned.m8n8.x2.shared.b16 {%0,%1}, [%2];"
                 : "=r"(r0), "=r"(r1) : "r"(a));
}
__device__ __forceinline__ void mma16816(float* c, uint32_t a0, uint32_t a1,
                                         uint32_t a2, uint32_t a3,
                                         uint32_t b0, uint32_t b1) {
    asm volatile(
        "mma.sync.aligned.m16n8k16.row.col.f32.f16.f16.f32 "
        "{%0,%1,%2,%3}, {%4,%5,%6,%7}, {%8,%9}, {%0,%1,%2,%3};"
        : "+f"(c[0]), "+f"(c[1]), "+f"(c[2]), "+f"(c[3])
        : "r"(a0), "r"(a1), "r"(a2), "r"(a3), "r"(b0), "r"(b1));
}

__global__ void __launch_bounds__(THREADS, 1)
mlp_kernel(const float* __restrict__ coords,
           const float* __restrict__ W0,
           const float* __restrict__ b0,
           const float* __restrict__ bh,
           const float* __restrict__ Wout,
           const float* __restrict__ bout,
           float* __restrict__ out,
           int Ntot)
{
    extern __shared__ char smem_raw[];
    char* sm = (char*)(((uintptr_t)smem_raw + 1023) & ~(uintptr_t)1023);
    const uint32_t sb = s2u(sm);
    const int tid = threadIdx.x;
    const int s = blockIdx.y;
    const int base = blockIdx.x * TILE_M;

    // ---- stage W0, b0, bh(0) and B(0) ----
    {
        const float* w0g = W0 + (size_t)s * 3 * HDIM;
        #pragma unroll
        for (int i = tid; i < 3 * HDIM; i += THREADS)
            ((float*)(sm + SM_W0))[i] = w0g[i];
        ((float*)(sm + SM_B0))[tid] = b0[(size_t)s * HDIM + tid];
        ((float*)(sm + SM_BH))[tid] = bh[(size_t)s * NLAY * HDIM + tid];
        const uint4* src = (const uint4*)(g_Bw + ((size_t)(s * NLAY) << 16));
        uint4* dst = (uint4*)(sm + SM_B);
        #pragma unroll 8
        for (int i = tid; i < 8192; i += THREADS) dst[i] = src[i];
    }
    __syncthreads();

    // ---- layer 0: [128x3]@[3x256] + softplus -> swizzled A tile ----
    {
        const int p = tid & 127;
        const int half = tid >> 7;
        float c0 = 0.f, c1 = 0.f, c2 = 0.f;
        if (base + p < Ntot) {
            const float* cp = coords + (size_t)(base + p) * 3;
            c0 = cp[0]; c1 = cp[1]; c2 = cp[2];
        }
        const float* sw0 = (const float*)(sm + SM_W0);
        const float* sb0 = (const float*)(sm + SM_B0);
        const uint32_t arow = (uint32_t)((p >> 3) * 1024 + (p & 7) * 128);
        const uint32_t axor = (uint32_t)((p & 7) * 16);
        #pragma unroll 8
        for (int j = half * 128; j < half * 128 + 128; j += 2) {
            float v0 = sb0[j]   + c0 * sw0[j]   + c1 * sw0[256 + j]   + c2 * sw0[512 + j];
            float v1 = sb0[j+1] + c0 * sw0[j+1] + c1 * sw0[256 + j+1] + c2 * sw0[512 + j+1];
            uint32_t rel = arow + (uint32_t)((j >> 6) * 16384)
                         + ((uint32_t)((j & 63) * 2) ^ axor);
            *(__half2*)(sm + SM_A + rel) = sp2(v0, v1);
        }
    }
    __syncthreads();

    // ---- warp tiling: 2 (M) x 4 (N); warp tile 64x64 ----
    const int wid = tid >> 5, ln = tid & 31;
    const int wm = wid & 1, wn = wid >> 1;

    // A ldmatrix lane addressing (SW128 decomposed: XOR term is lane-constant)
    uint32_t a_rel[4];
    {
        int mrow = wm * 64 + (ln & 15);
        #pragma unroll
        for (int mf = 0; mf < 4; mf++) {
            int m = mrow + mf * 16;
            a_rel[mf] = (uint32_t)(SM_A + (m >> 3) * 1024 + (m & 7) * 128);
        }
    }
    const uint32_t a_xor = (uint32_t)((ln & 7) * 16);
    const int akoff = (ln & 16) ? 8 : 0;
    // B ldmatrix lane addressing: j = wn*64 + nf*8 + (ln&7) -> base + nf*1024
    const uint32_t b_rel0 = (uint32_t)(SM_B + wn * 8192 + (ln & 7) * 128);
    const uint32_t b_xor = (uint32_t)((ln & 7) * 16);
    const int bkoff = (ln & 8) ? 8 : 0;

    float acc[128];

    for (int layer = 0; layer < NLAY; layer++) {
        #pragma unroll
        for (int i = 0; i < 128; i++) acc[i] = 0.f;

        #pragma unroll 2
        for (int ks = 0; ks < 16; ks++) {
            uint32_t af[16];
            const int ka = ks * 16 + akoff;
            const uint32_t aterm = (uint32_t)((ka >> 6) * 16384)
                                 + ((uint32_t)((ka & 63) * 2) ^ a_xor);
            #pragma unroll
            for (int mf = 0; mf < 4; mf++)
                ldsm_x4(af[mf*4], af[mf*4+1], af[mf*4+2], af[mf*4+3],
                        sb + a_rel[mf] + aterm);
            const int kb = ks * 16 + bkoff;
            uint32_t baddr = sb + b_rel0 + (uint32_t)((kb >> 6) * 32768)
                           + ((uint32_t)((kb & 63) * 2) ^ b_xor);
            #pragma unroll
            for (int nf = 0; nf < 8; nf++) {
                uint32_t br0, br1;
                ldsm_x2(br0, br1, baddr);
                baddr += 1024;
                #pragma unroll
                for (int mf = 0; mf < 4; mf++)
                    mma16816(&acc[(mf * 8 + nf) * 4],
                             af[mf*4], af[mf*4+1], af[mf*4+2], af[mf*4+3],
                             br0, br1);
            }
        }
        __syncthreads();   // all warps done reading A and B

        if (layer < NLAY - 1) {
            // prefetch next B tile + next bias (into the other bias buffer)
            const uint4* src = (const uint4*)(g_Bw + ((size_t)(s * NLAY + layer + 1) << 16));
            uint4* dst = (uint4*)(sm + SM_B);
            #pragma unroll 8
            for (int i = tid; i < 8192; i += THREADS) dst[i] = src[i];
            ((float*)(sm + SM_BH + ((layer + 1) & 1) * 1024))[tid] =
                bh[(size_t)(s * NLAY + layer + 1) * HDIM + tid];

            // epilogue: bias + softplus -> next A tile (in place)
            const float* sbh = (const float*)(sm + SM_BH + (layer & 1) * 1024);
            #pragma unroll
            for (int mf = 0; mf < 4; mf++) {
                const int mlo = wm * 64 + mf * 16 + (ln >> 2);
                const uint32_t alo = (uint32_t)(SM_A + (mlo >> 3) * 1024 + (mlo & 7) * 128);
                const uint32_t xlo = (uint32_t)((mlo & 7) * 16);  // same for mlo+8
                #pragma unroll
                for (int nf = 0; nf < 8; nf++) {
                    const int n0 = wn * 64 + nf * 8 + (ln & 3) * 2;
                    const float bv0 = sbh[n0], bv1 = sbh[n0 + 1];
                    const float* a4 = &acc[(mf * 8 + nf) * 4];
                    const uint32_t kt = (uint32_t)((n0 >> 6) * 16384)
                                      + ((uint32_t)((n0 & 63) * 2) ^ xlo);
                    *(__half2*)(sm + alo + kt)        = sp2(a4[0] + bv0, a4[1] + bv1);
                    *(__half2*)(sm + alo + 1024 + kt) = sp2(a4[2] + bv0, a4[3] + bv1);
                }
            }
            __syncthreads();
        } else {
            // final layer: softplus * Wout, fused 256->1 dot
            const float* sbh = (const float*)(sm + SM_BH + (layer & 1) * 1024);
            const float* wog = Wout + (size_t)s * HDIM;
            float rsum[8];
            #pragma unroll
            for (int mf = 0; mf < 4; mf++) {
                float lo = 0.f, hi = 0.f;
                #pragma unroll
                for (int nf = 0; nf < 8; nf++) {
                    const int n0 = wn * 64 + nf * 8 + (ln & 3) * 2;
                    const float bv0 = sbh[n0], bv1 = sbh[n0 + 1];
                    const float w0v = __ldg(wog + n0), w1v = __ldg(wog + n0 + 1);
                    const float* a4 = &acc[(mf * 8 + nf) * 4];
                    lo += softplusf(a4[0] + bv0) * w0v + softplusf(a4[1] + bv1) * w1v;
                    hi += softplusf(a4[2] + bv0) * w0v + softplusf(a4[3] + bv1) * w1v;
                }
                rsum[mf * 2] = lo;
                rsum[mf * 2 + 1] = hi;
            }
            #pragma unroll
            for (int i = 0; i < 8; i++) {
                rsum[i] += __shfl_xor_sync(0xffffffffu, rsum[i], 1);
                rsum[i] += __shfl_xor_sync(0xffffffffu, rsum[i], 2);
            }
            float* red = (float*)(sm + SM_RED);
            if ((ln & 3) == 0) {
                #pragma unroll
                for (int mf = 0; mf < 4; mf++) {
                    const int mlo = wm * 64 + mf * 16 + (ln >> 2);
                    red[wn * 128 + mlo]     = rsum[mf * 2];
                    red[wn * 128 + mlo + 8] = rsum[mf * 2 + 1];
                }
            }
            __syncthreads();
            if (tid < 128 && base + tid < Ntot) {
                float v = red[tid] + red[128 + tid] + red[256 + tid] + red[384 + tid]
                        + __ldg(bout + s);
                out[(size_t)(base + tid) * NSER + s] = v;
            }
        }
    }
}

extern "C" void kernel_launch(void* const* d_in, const int* in_sizes, int n_in,
                              void* d_out, int out_size) {
    const float* coords = (const float*)d_in[0];
    const float* W0     = (const float*)d_in[1];
    const float* b0     = (const float*)d_in[2];
    const float* Wh     = (const float*)d_in[3];
    const float* bh     = (const float*)d_in[4];
    const float* Wout   = (const float*)d_in[5];
    const float* bout   = (const float*)d_in[6];
    const int Npts = in_sizes[0] / 3;

    cudaFuncSetAttribute(mlp_kernel, cudaFuncAttributeMaxDynamicSharedMemorySize,
                         SMEM_BYTES);

    const int wtotal = NSER * NLAY * HDIM * HDIM;
    prep_weights<<<(wtotal + 255) / 256, 256>>>(Wh);

    dim3 grid((Npts + TILE_M - 1) / TILE_M, NSER);
    mlp_kernel<<<grid, THREADS, SMEM_BYTES>>>(coords, W0, b0, bh, Wout, bout,
                                              (float*)d_out, Npts);

    // reference returns (output, coords): echo coords after the [N,S] block
    long long need = (long long)Npts * NSER + (long long)Npts * 3;
    if ((long long)out_size >= need) {
        cudaMemcpyAsync((float*)d_out + (size_t)Npts * NSER, coords,
                        sizeof(float) * (size_t)Npts * 3,
                        cudaMemcpyDeviceToDevice, 0);
    }
}

// round 6
// speedup vs baseline: 1.6374x; 1.6374x over previous
#include <cuda_runtime.h>
#include <cuda_fp16.h>
#include <cstdint>

#define NSER 8
#define NLAY 4
#define HDIM 256
#define TILE_M 128
#define THREADS 512

// ---- smem layout (byte offsets from 1024-aligned base) ----
#define SM_A    0                       // 128x256 fp16, SW128 blocked atoms (65536 B)
#define SM_B    65536                   // 256x256 fp16, SW128 blocked atoms (131072 B)
#define SM_BH   196608                  // bias double buffer 2 x 1024 B
#define SM_W0   198656                  // W0 stage 3072 B (reused as reduction buf)
#define SM_B0   201728                  // b0 stage 1024 B
#define SM_RED  SM_W0                   // 512 floats (2048 B), reuse W0 region
#define SMEM_BYTES (201728 + 1024 + 1024)

// Pre-swizzled fp16 weight tiles: [s*4+l] tiles, each 256(out j) x 256(in k)
__device__ __half g_Bw[(size_t)NSER * NLAY * HDIM * HDIM];

__device__ __forceinline__ uint32_t swz(uint32_t o) { return o ^ ((o >> 3) & 0x70); }

__device__ __forceinline__ uint32_t b_off(int j, int k) {
    uint32_t o = ((uint32_t)(j >> 3) + (uint32_t)(k >> 6) * 32u) * 1024u
               + (uint32_t)(j & 7) * 128u + (uint32_t)(k & 63) * 2u;
    return swz(o);
}

__device__ __forceinline__ uint32_t s2u(const void* p) {
    uint32_t a;
    asm("{ .reg .u64 t; cvta.to.shared.u64 t, %1; cvt.u32.u64 %0, t; }" : "=r"(a) : "l"(p));
    return a;
}

__device__ __forceinline__ float softplusf(float x) {
    float ax = fabsf(x), u, lg;
    asm("ex2.approx.ftz.f32 %0, %1;" : "=f"(u) : "f"(-1.4426950408889634f * ax));
    asm("lg2.approx.ftz.f32 %0, %1;" : "=f"(lg) : "f"(1.0f + u));
    return fmaxf(x, 0.0f) + 0.6931471805599453f * lg;
}

__device__ __forceinline__ __half2 sp2(float a, float b) {
    return __floats2half2_rn(softplusf(a), softplusf(b));
}

// ---- prep: fp32 Wh[s][l][k][j] (k=in, j=out) -> fp16 pre-swizzled B images ----
__global__ void prep_weights(const float* __restrict__ Wh) {
    int idx = blockIdx.x * blockDim.x + threadIdx.x;
    if (idx >= NSER * NLAY * HDIM * HDIM) return;
    int t = idx >> 16;
    int r = idx & 0xFFFF;
    int k = r >> 8;
    int j = r & 0xFF;
    float w = Wh[((size_t)t << 16) + (k << 8) + j];
    char* base = (char*)g_Bw + (size_t)t * 131072;
    *(__half*)(base + b_off(j, k)) = __float2half_rn(w);
}

__device__ __forceinline__ void ldsm_x4(uint32_t& r0, uint32_t& r1, uint32_t& r2,
                                        uint32_t& r3, uint32_t a) {
    asm volatile("ldmatrix.sync.aligned.m8n8.x4.shared.b16 {%0,%1,%2,%3}, [%4];"
                 : "=r"(r0), "=r"(r1), "=r"(r2), "=r"(r3) : "r"(a));
}
__device__ __forceinline__ void mma16816(float* c, uint32_t a0, uint32_t a1,
                                         uint32_t a2, uint32_t a3,
                                         uint32_t b0, uint32_t b1) {
    asm volatile(
        "mma.sync.aligned.m16n8k16.row.col.f32.f16.f16.f32 "
        "{%0,%1,%2,%3}, {%4,%5,%6,%7}, {%8,%9}, {%0,%1,%2,%3};"
        : "+f"(c[0]), "+f"(c[1]), "+f"(c[2]), "+f"(c[3])
        : "r"(a0), "r"(a1), "r"(a2), "r"(a3), "r"(b0), "r"(b1));
}

__device__ __forceinline__ void cp16(uint32_t saddr, const void* g) {
    asm volatile("cp.async.cg.shared.global [%0], [%1], 16;"
                 :: "r"(saddr), "l"(g) : "memory");
}
__device__ __forceinline__ void cp_commit() {
    asm volatile("cp.async.commit_group;" ::: "memory");
}
__device__ __forceinline__ void cp_wait0() {
    asm volatile("cp.async.wait_group 0;" ::: "memory");
}

// copy one 131072-B pre-swizzled B tile into smem via cp.async (16 B x 16/thread)
__device__ __forceinline__ void issue_B_copy(uint32_t sb, const __half* gsrc, int tid) {
    const char* g = (const char*)gsrc;
    uint32_t d = sb + SM_B + (uint32_t)tid * 16u;
    #pragma unroll
    for (int i = 0; i < 16; i++)
        cp16(d + (uint32_t)i * 8192u, g + (size_t)tid * 16 + (size_t)i * 8192);
    cp_commit();
}

__global__ void __launch_bounds__(THREADS, 1)
mlp_kernel(const float* __restrict__ coords,
           const float* __restrict__ W0,
           const float* __restrict__ b0,
           const float* __restrict__ bh,
           const float* __restrict__ Wout,
           const float* __restrict__ bout,
           float* __restrict__ out,
           int Ntot)
{
    extern __shared__ char smem_raw[];
    char* sm = (char*)(((uintptr_t)smem_raw + 1023) & ~(uintptr_t)1023);
    const uint32_t sb = s2u(sm);
    const int tid = threadIdx.x;
    const int s = blockIdx.y;
    const int base = blockIdx.x * TILE_M;

    // ---- kick off B(0) copy, stage W0/b0/bh(0) (strided: FULL coverage) ----
    issue_B_copy(sb, g_Bw + ((size_t)(s * NLAY) << 16), tid);
    {
        const float* w0g = W0 + (size_t)s * 3 * HDIM;
        #pragma unroll
        for (int i = tid; i < 3 * HDIM; i += THREADS)
            ((float*)(sm + SM_W0))[i] = w0g[i];
        if (tid < HDIM) {
            ((float*)(sm + SM_B0))[tid] = b0[(size_t)s * HDIM + tid];
            ((float*)(sm + SM_BH))[tid] = bh[(size_t)s * NLAY * HDIM + tid];
        }
    }
    __syncthreads();

    // ---- layer 0: [128x3]@[3x256] + softplus -> swizzled A tile ----
    {
        const int p = tid & 127;
        const int q = tid >> 7;            // 0..3 -> which 64-col k-block
        float c0 = 0.f, c1 = 0.f, c2 = 0.f;
        if (base + p < Ntot) {
            const float* cp = coords + (size_t)(base + p) * 3;
            c0 = cp[0]; c1 = cp[1]; c2 = cp[2];
        }
        const float* sw0 = (const float*)(sm + SM_W0);
        const float* sb0 = (const float*)(sm + SM_B0);
        const uint32_t arow = (uint32_t)((p >> 3) * 1024 + (p & 7) * 128)
                            + (uint32_t)(q * 16384);
        const uint32_t axor = (uint32_t)((p & 7) * 16);
        #pragma unroll 8
        for (int j = q * 64; j < q * 64 + 64; j += 2) {
            float v0 = sb0[j]   + c0 * sw0[j]   + c1 * sw0[256 + j]   + c2 * sw0[512 + j];
            float v1 = sb0[j+1] + c0 * sw0[j+1] + c1 * sw0[256 + j+1] + c2 * sw0[512 + j+1];
            uint32_t rel = arow + ((uint32_t)((j & 63) * 2) ^ axor);
            *(__half2*)(sm + SM_A + rel) = sp2(v0, v1);
        }
    }
    cp_wait0();
    __syncthreads();

    // ---- warp tiling: 4 (M) x 4 (N); warp tile 32x64 ----
    const int wid = tid >> 5, ln = tid & 31;
    const int wm = wid & 3, wn = wid >> 2;

    uint32_t a_rel[2];
    {
        #pragma unroll
        for (int mf = 0; mf < 2; mf++) {
            int m = wm * 32 + mf * 16 + (ln & 15);
            a_rel[mf] = (uint32_t)(SM_A + (m >> 3) * 1024 + (m & 7) * 128);
        }
    }
    const uint32_t a_xor = (uint32_t)((ln & 7) * 16);
    const int akoff = (ln & 16) ? 8 : 0;
    // B x4: lanes 0-15 -> nf block, lanes 16-31 -> nf+1 block (j+8 -> +1024 B)
    const uint32_t b_rel0 = (uint32_t)(SM_B + wn * 8192 + (ln & 7) * 128
                                       + ((ln & 16) ? 1024 : 0));
    const uint32_t b_xor = (uint32_t)((ln & 7) * 16);
    const int bkoff = (ln & 8) ? 8 : 0;

    float acc[64];

    for (int layer = 0; layer < NLAY; layer++) {
        #pragma unroll
        for (int i = 0; i < 64; i++) acc[i] = 0.f;

        #pragma unroll 2
        for (int ks = 0; ks < 16; ks++) {
            uint32_t af[8];
            const int ka = ks * 16 + akoff;
            const uint32_t aterm = (uint32_t)((ka >> 6) * 16384)
                                 + ((uint32_t)((ka & 63) * 2) ^ a_xor);
            #pragma unroll
            for (int mf = 0; mf < 2; mf++)
                ldsm_x4(af[mf*4], af[mf*4+1], af[mf*4+2], af[mf*4+3],
                        sb + a_rel[mf] + aterm);
            const int kb = ks * 16 + bkoff;
            uint32_t baddr = sb + b_rel0 + (uint32_t)((kb >> 6) * 32768)
                           + ((uint32_t)((kb & 63) * 2) ^ b_xor);
            #pragma unroll
            for (int nf2 = 0; nf2 < 4; nf2++) {
                uint32_t br0, br1, br2, br3;
                ldsm_x4(br0, br1, br2, br3, baddr);
                baddr += 2048;
                #pragma unroll
                for (int mf = 0; mf < 2; mf++) {
                    mma16816(&acc[(mf * 8 + nf2 * 2) * 4],
                             af[mf*4], af[mf*4+1], af[mf*4+2], af[mf*4+3], br0, br1);
                    mma16816(&acc[(mf * 8 + nf2 * 2 + 1) * 4],
                             af[mf*4], af[mf*4+1], af[mf*4+2], af[mf*4+3], br2, br3);
                }
            }
        }
        __syncthreads();   // all warps done reading A and B

        if (layer < NLAY - 1) {
            // async-prefetch next B tile + next bias; overlaps with epilogue MUFU
            issue_B_copy(sb, g_Bw + ((size_t)(s * NLAY + layer + 1) << 16), tid);
            if (tid < HDIM)
                ((float*)(sm + SM_BH + ((layer + 1) & 1) * 1024))[tid] =
                    bh[(size_t)(s * NLAY + layer + 1) * HDIM + tid];

            // epilogue: bias + softplus -> next A tile (in place)
            const float* sbh = (const float*)(sm + SM_BH + (layer & 1) * 1024);
            #pragma unroll
            for (int mf = 0; mf < 2; mf++) {
                const int mlo = wm * 32 + mf * 16 + (ln >> 2);
                const uint32_t alo = (uint32_t)(SM_A + (mlo >> 3) * 1024 + (mlo & 7) * 128);
                const uint32_t xlo = (uint32_t)((mlo & 7) * 16);
                #pragma unroll
                for (int nf = 0; nf < 8; nf++) {
                    const int n0 = wn * 64 + nf * 8 + (ln & 3) * 2;
                    const float bv0 = sbh[n0], bv1 = sbh[n0 + 1];
                    const float* a4 = &acc[(mf * 8 + nf) * 4];
                    const uint32_t kt = (uint32_t)((n0 >> 6) * 16384)
                                      + ((uint32_t)((n0 & 63) * 2) ^ xlo);
                    *(__half2*)(sm + alo + kt)        = sp2(a4[0] + bv0, a4[1] + bv1);
                    *(__half2*)(sm + alo + 1024 + kt) = sp2(a4[2] + bv0, a4[3] + bv1);
                }
            }
            cp_wait0();
            __syncthreads();
        } else {
            // final layer: softplus * Wout, fused 256->1 dot
            const float* sbh = (const float*)(sm + SM_BH + (layer & 1) * 1024);
            const float* wog = Wout + (size_t)s * HDIM;
            float rsum[4];
            #pragma unroll
            for (int mf = 0; mf < 2; mf++) {
                float lo = 0.f, hi = 0.f;
                #pragma unroll
                for (int nf = 0; nf < 8; nf++) {
                    const int n0 = wn * 64 + nf * 8 + (ln & 3) * 2;
                    const float bv0 = sbh[n0], bv1 = sbh[n0 + 1];
                    const float w0v = __ldg(wog + n0), w1v = __ldg(wog + n0 + 1);
                    const float* a4 = &acc[(mf * 8 + nf) * 4];
                    lo += softplusf(a4[0] + bv0) * w0v + softplusf(a4[1] + bv1) * w1v;
                    hi += softplusf(a4[2] + bv0) * w0v + softplusf(a4[3] + bv1) * w1v;
                }
                rsum[mf * 2] = lo;
                rsum[mf * 2 + 1] = hi;
            }
            #pragma unroll
            for (int i = 0; i < 4; i++) {
                rsum[i] += __shfl_xor_sync(0xffffffffu, rsum[i], 1);
                rsum[i] += __shfl_xor_sync(0xffffffffu, rsum[i], 2);
            }
            float* red = (float*)(sm + SM_RED);
            if ((ln & 3) == 0) {
                #pragma unroll
                for (int mf = 0; mf < 2; mf++) {
                    const int mlo = wm * 32 + mf * 16 + (ln >> 2);
                    red[wn * 128 + mlo]     = rsum[mf * 2];
                    red[wn * 128 + mlo + 8] = rsum[mf * 2 + 1];
                }
            }
            __syncthreads();
            if (tid < 128 && base + tid < Ntot) {
                float v = red[tid] + red[128 + tid] + red[256 + tid] + red[384 + tid]
                        + __ldg(bout + s);
                out[(size_t)(base + tid) * NSER + s] = v;
            }
        }
    }
}

extern "C" void kernel_launch(void* const* d_in, const int* in_sizes, int n_in,
                              void* d_out, int out_size) {
    const float* coords = (const float*)d_in[0];
    const float* W0     = (const float*)d_in[1];
    const float* b0     = (const float*)d_in[2];
    const float* Wh     = (const float*)d_in[3];
    const float* bh     = (const float*)d_in[4];
    const float* Wout   = (const float*)d_in[5];
    const float* bout   = (const float*)d_in[6];
    const int Npts = in_sizes[0] / 3;

    cudaFuncSetAttribute(mlp_kernel, cudaFuncAttributeMaxDynamicSharedMemorySize,
                         SMEM_BYTES);

    const int wtotal = NSER * NLAY * HDIM * HDIM;
    prep_weights<<<(wtotal + 255) / 256, 256>>>(Wh);

    dim3 grid((Npts + TILE_M - 1) / TILE_M, NSER);
    mlp_kernel<<<grid, THREADS, SMEM_BYTES>>>(coords, W0, b0, bh, Wout, bout,
                                              (float*)d_out, Npts);

    long long need = (long long)Npts * NSER + (long long)Npts * 3;
    if ((long long)out_size >= need) {
        cudaMemcpyAsync((float*)d_out + (size_t)Npts * NSER, coords,
                        sizeof(float) * (size_t)Npts * 3,
                        cudaMemcpyDeviceToDevice, 0);
    }
}